// round 12
// baseline (speedup 1.0000x reference)
#include <cuda_runtime.h>
#include <cuda_bf16.h>
#include <cstdint>

// Problem constants (fixed by the dataset)
#define MAXN 100000
#define MAXE 600000
#define DF   128            // feature dim (in == hid == 128)

// ---------------------------------------------------------------------------
// Scratch (no allocations allowed -> __device__ globals)
// ---------------------------------------------------------------------------
__device__ float g_z[(size_t)MAXN * DF];    // z_pre (linear output) of current layer
__device__ float g_agg[(size_t)MAXN * DF];  // aggregation accumulator / layer output
__device__ int   g_deg[MAXN];
__device__ float g_dinv[MAXN];
// W split into bf16 hi/lo, stored TRANSPOSED: g_Bhi[n*DF + k] = hi(W[k][n])
__device__ __nv_bfloat16 g_Bhi[DF * DF];
__device__ __nv_bfloat16 g_Blo[DF * DF];

// ---------------------------------------------------------------------------
// Degree / normalization
// ---------------------------------------------------------------------------
__global__ void deg_init_kernel(int n) {
    int i = blockIdx.x * blockDim.x + threadIdx.x;
    if (i < n) g_deg[i] = 1;   // self-loop
}

__global__ void deg_count_kernel(const int* __restrict__ dst, int E) {
    int e = blockIdx.x * blockDim.x + threadIdx.x;
    if (e < E) atomicAdd(&g_deg[dst[e]], 1);
}

__global__ void dinv_kernel(int n) {
    int i = blockIdx.x * blockDim.x + threadIdx.x;
    if (i < n) g_dinv[i] = rsqrtf((float)g_deg[i]);
}

// ---------------------------------------------------------------------------
// W split + transpose: g_Bhi[n*DF+k] = bf16_hi(W[k][n]), g_Blo = bf16 residual
// ---------------------------------------------------------------------------
__global__ void wsplit_kernel(const float* __restrict__ W) {
    int i = blockIdx.x * blockDim.x + threadIdx.x;   // 16384 elements
    if (i >= DF * DF) return;
    int k = i / DF, n = i % DF;
    float f = W[i];
    __nv_bfloat16 h = __float2bfloat16(f);
    float r = f - __bfloat162float(h);
    g_Bhi[n * DF + k] = h;
    g_Blo[n * DF + k] = __float2bfloat16(r);
}

// ---------------------------------------------------------------------------
// PTX helpers (plain sm_80+ features only — NO 'a'-suffix instructions;
// this build environment targets compute_103, which rejects tcgen05/TMEM)
// ---------------------------------------------------------------------------
__device__ __forceinline__ uint32_t smem_to_u32(const void* smem_ptr) {
    uint32_t addr;
    asm("{ .reg .u64 tmp; cvta.to.shared.u64 tmp, %1; cvt.u32.u64 %0, tmp; }"
        : "=r"(addr) : "l"(smem_ptr));
    return addr;
}

#define LDSM_X4(R0, R1, R2, R3, addr) \
    asm volatile("ldmatrix.sync.aligned.m8n8.x4.shared.b16 {%0,%1,%2,%3}, [%4];" \
                 : "=r"(R0), "=r"(R1), "=r"(R2), "=r"(R3) : "r"(addr))

__device__ __forceinline__ void mma_bf16(float* d, const uint32_t* a,
                                         uint32_t b0, uint32_t b1) {
    asm volatile(
        "mma.sync.aligned.m16n8k16.row.col.f32.bf16.bf16.f32 "
        "{%0,%1,%2,%3}, {%4,%5,%6,%7}, {%8,%9}, {%0,%1,%2,%3};"
        : "+f"(d[0]), "+f"(d[1]), "+f"(d[2]), "+f"(d[3])
        : "r"(a[0]), "r"(a[1]), "r"(a[2]), "r"(a[3]), "r"(b0), "r"(b1));
}

__device__ __forceinline__ uint32_t pack_bf2(__nv_bfloat16 a, __nv_bfloat16 b) {
    __nv_bfloat162 t;
    t.x = a; t.y = b;
    return *reinterpret_cast<uint32_t*>(&t);
}

// ---------------------------------------------------------------------------
// SMEM layout: 4 tiles of 128 rows x 128 bf16, row stride padded to 272 bytes
// (128*2 + 16). 272 B = 68 banks -> consecutive rows start 4 banks apart, so
// ldmatrix 8-row phases and 8B staging stores are bank-conflict free.
// ---------------------------------------------------------------------------
static constexpr int RSTRIDE   = 272;                 // bytes per tile row
static constexpr int TILE_SZ   = 128 * RSTRIDE;       // 34816 B
static constexpr int OFF_AH    = 0;
static constexpr int OFF_AL    = TILE_SZ;
static constexpr int OFF_BH    = 2 * TILE_SZ;
static constexpr int OFF_BL    = 3 * TILE_SZ;
static constexpr int SMEM_TOTAL = 4 * TILE_SZ;        // 139264 B

// ---------------------------------------------------------------------------
// Tensor-core GEMM via mma.sync (bf16-split 3-term fp32 emulation):
//   Zpre = act(A + preBias) @ W ;  Agg = Zpre * dinv^2  (self-loop init)
//   ASRC=0: A = Aext (x);  ASRC=1: A = g_agg (in-place safe: the block reads
//   only the rows it writes, and all reads precede the epilogue stores).
// Terms: Ah@Bh + Ah@Bl + Al@Bh. 256 threads, warp tile 32(M) x 64(N).
// ---------------------------------------------------------------------------
template<int ASRC, bool PRERELU>
__global__ void __launch_bounds__(256, 1)
gemm_mma_kernel(const float* __restrict__ Aext,
                const float* __restrict__ preBias,
                int M)
{
    extern __shared__ char smem[];
    const uint32_t sb = smem_to_u32(smem);
    const int tid  = threadIdx.x;
    const int wid  = tid >> 5;
    const int lane = tid & 31;
    const int rowBase = blockIdx.x * 128;

    const float* A = (ASRC == 0) ? Aext : g_agg;

    // ---- stage A: one warp per row, 8 warps -> 16 rows each ----
    float4 bb = make_float4(0.f, 0.f, 0.f, 0.f);
    if (PRERELU) bb = *(const float4*)(preBias + lane * 4);
    for (int r = wid; r < 128; r += 8) {
        int grow = rowBase + r;
        float4 v = make_float4(0.f, 0.f, 0.f, 0.f);
        if (grow < M) v = ((const float4*)(A + (size_t)grow * DF))[lane];
        if (PRERELU) {
            v.x = fmaxf(v.x + bb.x, 0.f);
            v.y = fmaxf(v.y + bb.y, 0.f);
            v.z = fmaxf(v.z + bb.z, 0.f);
            v.w = fmaxf(v.w + bb.w, 0.f);
        }
        __nv_bfloat16 hx = __float2bfloat16(v.x), hy = __float2bfloat16(v.y);
        __nv_bfloat16 hz = __float2bfloat16(v.z), hw = __float2bfloat16(v.w);
        __nv_bfloat16 lx = __float2bfloat16(v.x - __bfloat162float(hx));
        __nv_bfloat16 ly = __float2bfloat16(v.y - __bfloat162float(hy));
        __nv_bfloat16 lz = __float2bfloat16(v.z - __bfloat162float(hz));
        __nv_bfloat16 lw = __float2bfloat16(v.w - __bfloat162float(hw));
        uint32_t off = (uint32_t)(r * RSTRIDE + lane * 8);
        asm volatile("st.shared.v2.b32 [%0], {%1, %2};"
                     :: "r"(sb + OFF_AH + off),
                        "r"(pack_bf2(hx, hy)), "r"(pack_bf2(hz, hw)) : "memory");
        asm volatile("st.shared.v2.b32 [%0], {%1, %2};"
                     :: "r"(sb + OFF_AL + off),
                        "r"(pack_bf2(lx, ly)), "r"(pack_bf2(lz, lw)) : "memory");
    }

    // ---- stage B: W hi/lo, already [n][k] in global ----
    for (int n = wid; n < 128; n += 8) {
        uint2 hp = ((const uint2*)(g_Bhi + (size_t)n * DF))[lane];
        uint2 lp = ((const uint2*)(g_Blo + (size_t)n * DF))[lane];
        uint32_t off = (uint32_t)(n * RSTRIDE + lane * 8);
        asm volatile("st.shared.v2.b32 [%0], {%1, %2};"
                     :: "r"(sb + OFF_BH + off), "r"(hp.x), "r"(hp.y) : "memory");
        asm volatile("st.shared.v2.b32 [%0], {%1, %2};"
                     :: "r"(sb + OFF_BL + off), "r"(lp.x), "r"(lp.y) : "memory");
    }
    __syncthreads();

    // ---- warp tile: warp_m in 0..3 (32 M-rows), warp_n in 0..1 (64 N-cols) ----
    const int warp_m = wid & 3;
    const int warp_n = wid >> 2;
    const int m0 = warp_m * 32;
    const int n0 = warp_n * 64;

    float acc[2][8][4];
    #pragma unroll
    for (int i = 0; i < 2; i++)
        #pragma unroll
        for (int j = 0; j < 8; j++)
            #pragma unroll
            for (int q = 0; q < 4; q++) acc[i][j][q] = 0.f;

    // ldmatrix lane addressing: 16 rows (lane&15), k-half (lane>>4)
    const int lrow = lane & 15;
    const int lkof = (lane >> 4) * 16;

    #pragma unroll
    for (int p = 0; p < 3; p++) {
        const uint32_t aBase = sb + ((p == 2) ? OFF_AL : OFF_AH);
        const uint32_t bBase = sb + ((p == 1) ? OFF_BL : OFF_BH);
        #pragma unroll
        for (int ks = 0; ks < 8; ks++) {
            const int kb = ks * 32;   // 16 bf16 = 32 bytes
            uint32_t a[2][4];
            #pragma unroll
            for (int i = 0; i < 2; i++) {
                uint32_t addr = aBase + (uint32_t)((m0 + i * 16 + lrow) * RSTRIDE
                                                   + kb + lkof);
                LDSM_X4(a[i][0], a[i][1], a[i][2], a[i][3], addr);
            }
            uint32_t b[4][4];
            #pragma unroll
            for (int j2 = 0; j2 < 4; j2++) {
                uint32_t addr = bBase + (uint32_t)((n0 + j2 * 16 + lrow) * RSTRIDE
                                                   + kb + lkof);
                LDSM_X4(b[j2][0], b[j2][1], b[j2][2], b[j2][3], addr);
            }
            #pragma unroll
            for (int i = 0; i < 2; i++)
                #pragma unroll
                for (int j2 = 0; j2 < 4; j2++) {
                    mma_bf16(acc[i][j2 * 2 + 0], a[i], b[j2][0], b[j2][2]);
                    mma_bf16(acc[i][j2 * 2 + 1], a[i], b[j2][1], b[j2][3]);
                }
        }
    }

    // ---- epilogue: d-frag thread t holds C[m0+i*16+t/4(+8)][n0+j*8+(t&3)*2] ----
    #pragma unroll
    for (int i = 0; i < 2; i++) {
        #pragma unroll
        for (int h = 0; h < 2; h++) {              // h=0 -> rows +0, h=1 -> rows +8
            int grow = rowBase + m0 + i * 16 + h * 8 + (lane >> 2);
            if (grow >= M) continue;
            float di = g_dinv[grow];
            float d2 = di * di;
            size_t base = (size_t)grow * DF + n0 + (lane & 3) * 2;
            #pragma unroll
            for (int j = 0; j < 8; j++) {
                float2 v = make_float2(acc[i][j][h * 2 + 0], acc[i][j][h * 2 + 1]);
                *(float2*)(g_z + base + j * 8) = v;
                *(float2*)(g_agg + base + j * 8) = make_float2(v.x * d2, v.y * d2);
            }
        }
    }
}

// ---------------------------------------------------------------------------
// Edge scatter: one warp per edge.
//   g_agg[dst] += g_z[src] * (dinv[src]*dinv[dst]) via red.global.add.v4.f32
// ---------------------------------------------------------------------------
__global__ void scatter_kernel(const int* __restrict__ src,
                               const int* __restrict__ dst,
                               int E)
{
    int warp = (blockIdx.x * blockDim.x + threadIdx.x) >> 5;
    int lane = threadIdx.x & 31;
    if (warp >= E) return;
    int s = __ldg(src + warp);
    int d = __ldg(dst + warp);
    float norm = g_dinv[s] * g_dinv[d];
    float4 v = *(const float4*)(g_z + (size_t)s * DF + lane * 4);
    float* p = g_agg + (size_t)d * DF + lane * 4;
    asm volatile("red.global.add.v4.f32 [%0], {%1, %2, %3, %4};"
                 :: "l"(p), "f"(v.x * norm), "f"(v.y * norm),
                    "f"(v.z * norm), "f"(v.w * norm)
                 : "memory");
}

// ---------------------------------------------------------------------------
// Edge decode: out[e] = sum_f (z[src]+b2)[f] * (z[dst]+b2)[f], warp per edge
// ---------------------------------------------------------------------------
__global__ void edge_dot_kernel(const int* __restrict__ src,
                                const int* __restrict__ dst,
                                const float* __restrict__ bias,
                                float* __restrict__ out,
                                int E)
{
    int warp = (blockIdx.x * blockDim.x + threadIdx.x) >> 5;
    int lane = threadIdx.x & 31;
    if (warp >= E) return;
    int s = __ldg(src + warp);
    int d = __ldg(dst + warp);
    float4 bb = *(const float4*)(bias + lane * 4);
    float4 a  = *(const float4*)(g_agg + (size_t)s * DF + lane * 4);
    float4 b  = *(const float4*)(g_agg + (size_t)d * DF + lane * 4);
    float p = (a.x + bb.x) * (b.x + bb.x)
            + (a.y + bb.y) * (b.y + bb.y)
            + (a.z + bb.z) * (b.z + bb.z)
            + (a.w + bb.w) * (b.w + bb.w);
    #pragma unroll
    for (int o = 16; o > 0; o >>= 1)
        p += __shfl_xor_sync(0xffffffffu, p, o);
    if (lane == 0) out[warp] = p;
}

// ---------------------------------------------------------------------------
// kernel_launch
// Inputs (metadata order): x [N*128], edge_index [2*E], W1, b1, W2, b2
// ---------------------------------------------------------------------------
extern "C" void kernel_launch(void* const* d_in, const int* in_sizes, int n_in,
                              void* d_out, int out_size)
{
    const float* x  = (const float*)d_in[0];
    const int*   ei = (const int*)  d_in[1];
    const float* W1 = (const float*)d_in[2];
    const float* b1 = (const float*)d_in[3];
    const float* W2 = (const float*)d_in[4];
    const float* b2 = (const float*)d_in[5];

    int E = in_sizes[1] / 2;
    int N = in_sizes[0] / DF;
    if (N > MAXN) N = MAXN;
    if (E > MAXE) E = MAXE;

    const int* src = ei;
    const int* dst = ei + E;
    float* out = (float*)d_out;

    const int T = 256;

    cudaFuncSetAttribute(gemm_mma_kernel<0, false>,
                         cudaFuncAttributeMaxDynamicSharedMemorySize, SMEM_TOTAL);
    cudaFuncSetAttribute(gemm_mma_kernel<1, true>,
                         cudaFuncAttributeMaxDynamicSharedMemorySize, SMEM_TOTAL);

    // degrees & normalization
    deg_init_kernel<<<(N + T - 1) / T, T>>>(N);
    deg_count_kernel<<<(E + T - 1) / T, T>>>(dst, E);
    dinv_kernel<<<(N + T - 1) / T, T>>>(N);

    int gemm_blocks = (N + 127) / 128;
    int edge_blocks = (E + 7) / 8;   // 8 warps per block, warp per edge

    // ---- Layer 1: z = GCNConv(x, W1, b1); relu+bias deferred into GEMM2 load ----
    wsplit_kernel<<<(DF * DF + T - 1) / T, T>>>(W1);
    gemm_mma_kernel<0, false><<<gemm_blocks, T, SMEM_TOTAL>>>(x, nullptr, N);
    scatter_kernel<<<edge_blocks, T>>>(src, dst, E);
    // g_agg = pre-bias layer-1 output

    // ---- Layer 2: z2 = GCNConv(relu(agg1 + b1), W2, b2) ----
    wsplit_kernel<<<(DF * DF + T - 1) / T, T>>>(W2);
    gemm_mma_kernel<1, true><<<gemm_blocks, T, SMEM_TOTAL>>>(nullptr, b1, N);
    scatter_kernel<<<edge_blocks, T>>>(src, dst, E);
    // g_agg = pre-bias layer-2 output (b2 fused into decode)

    // ---- Decode: per-edge dot of endpoint embeddings ----
    edge_dot_kernel<<<edge_blocks, T>>>(src, dst, b2, out, E);
}

// round 13
// speedup vs baseline: 1.3119x; 1.3119x over previous
#include <cuda_runtime.h>
#include <cstdint>

// Problem constants (fixed by the dataset)
#define MAXN 100000
#define MAXE 600000
#define DF   128            // feature dim (in == hid == 128)

// ---------------------------------------------------------------------------
// Scratch (no allocations allowed -> __device__ globals)
// ---------------------------------------------------------------------------
__device__ float g_y[(size_t)MAXN * DF];    // y = z_pre * dinv[row]  (GEMM output)
__device__ float g_agg[(size_t)MAXN * DF];  // S = y[i] + sum_{j->i} y[j]
__device__ int   g_deg[MAXN];
__device__ float g_dinv[MAXN];
// CSR (by destination node)
__device__ int   g_csr_src[MAXE];
__device__ int   g_off[MAXN + 1];
__device__ int   g_cur[MAXN];
__device__ int   g_bsum[128];
__device__ int   g_boff[128];

// ---------------------------------------------------------------------------
// Degree / normalization
// ---------------------------------------------------------------------------
__global__ void deg_init_kernel(int n) {
    int i = blockIdx.x * blockDim.x + threadIdx.x;
    if (i < n) g_deg[i] = 1;   // self-loop
}

__global__ void deg_count_kernel(const int* __restrict__ dst, int E) {
    int e = blockIdx.x * blockDim.x + threadIdx.x;
    if (e < E) atomicAdd(&g_deg[dst[e]], 1);
}

__global__ void dinv_kernel(int n) {
    int i = blockIdx.x * blockDim.x + threadIdx.x;
    if (i < n) g_dinv[i] = rsqrtf((float)g_deg[i]);
}

// ---------------------------------------------------------------------------
// CSR build: exclusive scan of cnt[i] = deg[i]-1 (in-edge count), then bucket
// fill. 3-kernel exact scan (block scan -> scan of block sums -> add offsets).
// ---------------------------------------------------------------------------
static constexpr int SCAN_B  = 1024;
static constexpr int SCAN_NB = (MAXN + SCAN_B - 1) / SCAN_B;   // 98

__global__ void scanA_kernel(int n) {
    __shared__ int sh[SCAN_B];
    int t = threadIdx.x, b = blockIdx.x;
    int i = b * SCAN_B + t;
    int v = (i < n) ? (g_deg[i] - 1) : 0;
    sh[t] = v;
    __syncthreads();
    #pragma unroll
    for (int o = 1; o < SCAN_B; o <<= 1) {
        int x = (t >= o) ? sh[t - o] : 0;
        __syncthreads();
        sh[t] += x;
        __syncthreads();
    }
    int incl = sh[t];
    if (i <= n) g_off[i] = incl - v;           // exclusive, pre-block-offset
    if (t == SCAN_B - 1) g_bsum[b] = incl;     // block total
}

__global__ void scanB_kernel(int nb) {
    __shared__ int sh[128];
    int t = threadIdx.x;
    sh[t] = (t < nb) ? g_bsum[t] : 0;
    __syncthreads();
    if (t == 0) {
        int run = 0;
        for (int b = 0; b < nb; b++) { int x = sh[b]; sh[b] = run; run += x; }
    }
    __syncthreads();
    if (t < nb) g_boff[t] = sh[t];
}

__global__ void scanC_kernel(int n) {
    int t = threadIdx.x, b = blockIdx.x;
    int i = b * SCAN_B + t;
    if (i <= n) {
        int o = g_off[i] + g_boff[b];
        g_off[i] = o;
        if (i < n) g_cur[i] = o;
    }
}

__global__ void csr_fill_kernel(const int* __restrict__ src,
                                const int* __restrict__ dst, int E) {
    int e = blockIdx.x * blockDim.x + threadIdx.x;
    if (e >= E) return;
    int s = src[e], d = dst[e];
    int pos = atomicAdd(&g_cur[d], 1);
    g_csr_src[pos] = s;
}

// ---------------------------------------------------------------------------
// Fused GEMM:  y = act(A) @ W * dinv[row]
//   ASRC = 0 : A = Aext (external input x)
//   ASRC = 1 : A[i][k] = relu(g_agg[i][k] * dinv[i] + preBias[k])
//              (g_agg holds raw sums S from the gather; the dinv factor of
//               the previous layer's aggregation is folded in here)
// Epilogue writes ONLY g_y = acc * dinv[row] (self-loop + symmetric norm
// pre-factored; the consumer applies the remaining dinv).
// Tile: 128x128 per block, K steps of 16, 256 threads, 8x8 per thread.
// ---------------------------------------------------------------------------
template<int ASRC, bool PRERELU>
__global__ void __launch_bounds__(256)
gemm_fused_kernel(const float* __restrict__ Aext,
                  const float* __restrict__ W,
                  const float* __restrict__ preBias,
                  int M)
{
    const int BM = 128, BK = 16;
    __shared__ float As[BK][BM];   // [k][m]
    __shared__ float Bs[BK][BM];   // [k][n]

    const float* A = (ASRC == 0) ? Aext : g_agg;

    int tid = threadIdx.x;
    int tx  = tid & 15;        // col group (8 cols each)
    int ty  = tid >> 4;        // row group (8 rows each)
    int rowBase = blockIdx.x * BM;

    float acc[8][8];
    #pragma unroll
    for (int i = 0; i < 8; i++)
        #pragma unroll
        for (int j = 0; j < 8; j++) acc[i][j] = 0.0f;

    for (int k0 = 0; k0 < DF; k0 += BK) {
        // --- load A tile: 128 rows x 16 k (512 float4, 2 per thread) ---
        #pragma unroll
        for (int it = 0; it < 2; ++it) {
            int q  = tid + it * 256;
            int r  = q >> 2;             // row within tile
            int kk = (q & 3) << 2;       // 0,4,8,12
            int grow = rowBase + r;
            float4 v = make_float4(0.f, 0.f, 0.f, 0.f);
            if (grow < M)
                v = *(const float4*)(A + (size_t)grow * DF + k0 + kk);
            if (PRERELU) {
                float di = g_dinv[grow < M ? grow : 0];
                float4 bb = *(const float4*)(preBias + k0 + kk);
                v.x = fmaxf(fmaf(v.x, di, bb.x), 0.f);
                v.y = fmaxf(fmaf(v.y, di, bb.y), 0.f);
                v.z = fmaxf(fmaf(v.z, di, bb.z), 0.f);
                v.w = fmaxf(fmaf(v.w, di, bb.w), 0.f);
                if (grow >= M) { v.x = v.y = v.z = v.w = 0.f; }
            }
            As[kk + 0][r] = v.x;
            As[kk + 1][r] = v.y;
            As[kk + 2][r] = v.z;
            As[kk + 3][r] = v.w;
        }
        // --- load W tile: 16 k-rows x 128 cols ---
        #pragma unroll
        for (int it = 0; it < 2; ++it) {
            int q = tid + it * 256;
            int r = q >> 5;              // 0..15
            int c = (q & 31) << 2;       // 0..124
            *(float4*)(&Bs[r][c]) = *(const float4*)(W + (size_t)(k0 + r) * DF + c);
        }
        __syncthreads();

        #pragma unroll
        for (int kk = 0; kk < BK; ++kk) {
            float ra[8], rb[8];
            #pragma unroll
            for (int i = 0; i < 8; i++) ra[i] = As[kk][ty * 8 + i];
            #pragma unroll
            for (int j = 0; j < 8; j++) rb[j] = Bs[kk][tx * 8 + j];
            #pragma unroll
            for (int i = 0; i < 8; i++)
                #pragma unroll
                for (int j = 0; j < 8; j++)
                    acc[i][j] = fmaf(ra[i], rb[j], acc[i][j]);
        }
        __syncthreads();
    }

    // --- epilogue: y = acc * dinv[row] (single-array store) ---
    #pragma unroll
    for (int i = 0; i < 8; i++) {
        int grow = rowBase + ty * 8 + i;
        if (grow >= M) continue;
        float di = g_dinv[grow];
        size_t base = (size_t)grow * DF + tx * 8;
        #pragma unroll
        for (int j = 0; j < 8; j += 4) {
            float4 v = make_float4(acc[i][j] * di, acc[i][j + 1] * di,
                                   acc[i][j + 2] * di, acc[i][j + 3] * di);
            *(float4*)(g_y + base + j) = v;
        }
    }
}

// ---------------------------------------------------------------------------
// CSR gather aggregation: warp per node.
//   S[i] = y[i] + sum_{e in in(i)} y[src[e]]        (no atomics, streaming out)
// ---------------------------------------------------------------------------
__global__ void gather_kernel(int N)
{
    int node = (blockIdx.x * blockDim.x + threadIdx.x) >> 5;
    int lane = threadIdx.x & 31;
    if (node >= N) return;
    int beg = g_off[node];
    int end = g_off[node + 1];
    float4 acc = ((const float4*)(g_y + (size_t)node * DF))[lane];   // self term
    for (int e = beg; e < end; e++) {
        int s = g_csr_src[e];
        float4 v = ((const float4*)(g_y + (size_t)s * DF))[lane];
        acc.x += v.x; acc.y += v.y; acc.z += v.z; acc.w += v.w;
    }
    ((float4*)(g_agg + (size_t)node * DF))[lane] = acc;
}

// ---------------------------------------------------------------------------
// Edge decode: z2[i] = S2[i]*dinv[i] + b2;  out[e] = <z2[src], z2[dst]>
// ---------------------------------------------------------------------------
__global__ void edge_dot_kernel(const int* __restrict__ src,
                                const int* __restrict__ dst,
                                const float* __restrict__ bias,
                                float* __restrict__ out,
                                int E)
{
    int warp = (blockIdx.x * blockDim.x + threadIdx.x) >> 5;
    int lane = threadIdx.x & 31;
    if (warp >= E) return;
    int s = __ldg(src + warp);
    int d = __ldg(dst + warp);
    float ds = g_dinv[s];
    float dd = g_dinv[d];
    float4 bb = *(const float4*)(bias + lane * 4);
    float4 a  = *(const float4*)(g_agg + (size_t)s * DF + lane * 4);
    float4 b  = *(const float4*)(g_agg + (size_t)d * DF + lane * 4);
    float p = fmaf(a.x, ds, bb.x) * fmaf(b.x, dd, bb.x)
            + fmaf(a.y, ds, bb.y) * fmaf(b.y, dd, bb.y)
            + fmaf(a.z, ds, bb.z) * fmaf(b.z, dd, bb.z)
            + fmaf(a.w, ds, bb.w) * fmaf(b.w, dd, bb.w);
    #pragma unroll
    for (int o = 16; o > 0; o >>= 1)
        p += __shfl_xor_sync(0xffffffffu, p, o);
    if (lane == 0) out[warp] = p;
}

// ---------------------------------------------------------------------------
// kernel_launch
// Inputs (metadata order): x [N*128], edge_index [2*E], W1, b1, W2, b2
// ---------------------------------------------------------------------------
extern "C" void kernel_launch(void* const* d_in, const int* in_sizes, int n_in,
                              void* d_out, int out_size)
{
    const float* x  = (const float*)d_in[0];
    const int*   ei = (const int*)  d_in[1];
    const float* W1 = (const float*)d_in[2];
    const float* b1 = (const float*)d_in[3];
    const float* W2 = (const float*)d_in[4];
    const float* b2 = (const float*)d_in[5];

    int E = in_sizes[1] / 2;
    int N = in_sizes[0] / DF;
    if (N > MAXN) N = MAXN;
    if (E > MAXE) E = MAXE;

    const int* src = ei;
    const int* dst = ei + E;
    float* out = (float*)d_out;

    const int T = 256;
    int nb = (N + SCAN_B - 1) / SCAN_B;

    // ---- degrees, normalization, CSR build ----
    deg_init_kernel<<<(N + T - 1) / T, T>>>(N);
    deg_count_kernel<<<(E + T - 1) / T, T>>>(dst, E);
    dinv_kernel<<<(N + T - 1) / T, T>>>(N);
    scanA_kernel<<<nb, SCAN_B>>>(N);
    scanB_kernel<<<1, 128>>>(nb);
    scanC_kernel<<<nb, SCAN_B>>>(N);
    csr_fill_kernel<<<(E + T - 1) / T, T>>>(src, dst, E);

    int gemm_blocks = (N + 127) / 128;
    int node_blocks = (N + 7) / 8;   // warp per node, 8 warps/block
    int edge_blocks = (E + 7) / 8;   // warp per edge

    // ---- Layer 1: y1 = (x @ W1) * dinv ; S1 = gather(y1) ----
    gemm_fused_kernel<0, false><<<gemm_blocks, T>>>(x, W1, nullptr, N);
    gather_kernel<<<node_blocks, T>>>(N);
    // g_agg = S1 (raw sums; dinv + b1 + relu applied in GEMM2's A-load)

    // ---- Layer 2: y2 = relu(S1*dinv + b1) @ W2 * dinv ; S2 = gather(y2) ----
    gemm_fused_kernel<1, true><<<gemm_blocks, T>>>(nullptr, W2, b1, N);
    gather_kernel<<<node_blocks, T>>>(N);
    // g_agg = S2 (dinv + b2 applied in decode)

    // ---- Decode: per-edge dot of endpoint embeddings ----
    edge_dot_kernel<<<edge_blocks, T>>>(src, dst, b2, out, E);
}

// round 14
// speedup vs baseline: 1.3120x; 1.0001x over previous
#include <cuda_runtime.h>
#include <cstdint>

// Problem constants (fixed by the dataset)
#define MAXN 100000
#define MAXE 600000
#define DF   128            // feature dim (in == hid == 128)

// ---------------------------------------------------------------------------
// Scratch (no allocations allowed -> __device__ globals)
// ---------------------------------------------------------------------------
__device__ float g_y[(size_t)MAXN * DF];    // y = z_pre * dinv[row]  (GEMM output)
__device__ float g_agg[(size_t)MAXN * DF];  // S = y[i] + sum_{j->i} y[j]
__device__ int   g_deg[MAXN];
__device__ float g_dinv[MAXN];
// CSR (by destination node)
__device__ int   g_csr_src[MAXE];
__device__ int   g_off[MAXN + 1];
__device__ int   g_cur[MAXN];
__device__ int   g_bsum[128];
__device__ int   g_boff[128];

// ---------------------------------------------------------------------------
// Degree / normalization
// ---------------------------------------------------------------------------
__global__ void deg_init_kernel(int n) {
    int i = blockIdx.x * blockDim.x + threadIdx.x;
    if (i < n) g_deg[i] = 1;   // self-loop
}

__global__ void deg_count_kernel(const int* __restrict__ dst, int E) {
    int e = blockIdx.x * blockDim.x + threadIdx.x;
    if (e < E) atomicAdd(&g_deg[dst[e]], 1);
}

__global__ void dinv_kernel(int n) {
    int i = blockIdx.x * blockDim.x + threadIdx.x;
    if (i < n) g_dinv[i] = rsqrtf((float)g_deg[i]);
}

// ---------------------------------------------------------------------------
// CSR build: exclusive scan of cnt[i] = deg[i]-1 (in-edge count), then bucket
// fill. 3-kernel exact scan (block scan -> scan of block sums -> add offsets).
// ---------------------------------------------------------------------------
static constexpr int SCAN_B  = 1024;
static constexpr int SCAN_NB = (MAXN + SCAN_B - 1) / SCAN_B;   // 98

__global__ void scanA_kernel(int n) {
    __shared__ int sh[SCAN_B];
    int t = threadIdx.x, b = blockIdx.x;
    int i = b * SCAN_B + t;
    int v = (i < n) ? (g_deg[i] - 1) : 0;
    sh[t] = v;
    __syncthreads();
    #pragma unroll
    for (int o = 1; o < SCAN_B; o <<= 1) {
        int x = (t >= o) ? sh[t - o] : 0;
        __syncthreads();
        sh[t] += x;
        __syncthreads();
    }
    int incl = sh[t];
    if (i <= n) g_off[i] = incl - v;           // exclusive, pre-block-offset
    if (t == SCAN_B - 1) g_bsum[b] = incl;     // block total
}

__global__ void scanB_kernel(int nb) {
    __shared__ int sh[128];
    int t = threadIdx.x;
    sh[t] = (t < nb) ? g_bsum[t] : 0;
    __syncthreads();
    if (t == 0) {
        int run = 0;
        for (int b = 0; b < nb; b++) { int x = sh[b]; sh[b] = run; run += x; }
    }
    __syncthreads();
    if (t < nb) g_boff[t] = sh[t];
}

__global__ void scanC_kernel(int n) {
    int t = threadIdx.x, b = blockIdx.x;
    int i = b * SCAN_B + t;
    if (i <= n) {
        int o = g_off[i] + g_boff[b];
        g_off[i] = o;
        if (i < n) g_cur[i] = o;
    }
}

__global__ void csr_fill_kernel(const int* __restrict__ src,
                                const int* __restrict__ dst, int E) {
    int e = blockIdx.x * blockDim.x + threadIdx.x;
    if (e >= E) return;
    int s = src[e], d = dst[e];
    int pos = atomicAdd(&g_cur[d], 1);
    g_csr_src[pos] = s;
}

// ---------------------------------------------------------------------------
// Fused GEMM:  y = act(A) @ W * dinv[row]
//   ASRC = 0 : A = Aext (external input x)
//   ASRC = 1 : A[i][k] = relu(g_agg[i][k] * dinv[i] + preBias[k])
//              (g_agg holds raw sums S from the gather; the dinv factor of
//               the previous layer's aggregation is folded in here)
// Epilogue writes ONLY g_y = acc * dinv[row] (self-loop + symmetric norm
// pre-factored; the consumer applies the remaining dinv).
// Tile: 128x128 per block, K steps of 16, 256 threads, 8x8 per thread.
// ---------------------------------------------------------------------------
template<int ASRC, bool PRERELU>
__global__ void __launch_bounds__(256)
gemm_fused_kernel(const float* __restrict__ Aext,
                  const float* __restrict__ W,
                  const float* __restrict__ preBias,
                  int M)
{
    const int BM = 128, BK = 16;
    __shared__ float As[BK][BM];   // [k][m]
    __shared__ float Bs[BK][BM];   // [k][n]

    const float* A = (ASRC == 0) ? Aext : g_agg;

    int tid = threadIdx.x;
    int tx  = tid & 15;        // col group (8 cols each)
    int ty  = tid >> 4;        // row group (8 rows each)
    int rowBase = blockIdx.x * BM;

    float acc[8][8];
    #pragma unroll
    for (int i = 0; i < 8; i++)
        #pragma unroll
        for (int j = 0; j < 8; j++) acc[i][j] = 0.0f;

    for (int k0 = 0; k0 < DF; k0 += BK) {
        // --- load A tile: 128 rows x 16 k (512 float4, 2 per thread) ---
        #pragma unroll
        for (int it = 0; it < 2; ++it) {
            int q  = tid + it * 256;
            int r  = q >> 2;             // row within tile
            int kk = (q & 3) << 2;       // 0,4,8,12
            int grow = rowBase + r;
            float4 v = make_float4(0.f, 0.f, 0.f, 0.f);
            if (grow < M)
                v = *(const float4*)(A + (size_t)grow * DF + k0 + kk);
            if (PRERELU) {
                float di = g_dinv[grow < M ? grow : 0];
                float4 bb = *(const float4*)(preBias + k0 + kk);
                v.x = fmaxf(fmaf(v.x, di, bb.x), 0.f);
                v.y = fmaxf(fmaf(v.y, di, bb.y), 0.f);
                v.z = fmaxf(fmaf(v.z, di, bb.z), 0.f);
                v.w = fmaxf(fmaf(v.w, di, bb.w), 0.f);
                if (grow >= M) { v.x = v.y = v.z = v.w = 0.f; }
            }
            As[kk + 0][r] = v.x;
            As[kk + 1][r] = v.y;
            As[kk + 2][r] = v.z;
            As[kk + 3][r] = v.w;
        }
        // --- load W tile: 16 k-rows x 128 cols ---
        #pragma unroll
        for (int it = 0; it < 2; ++it) {
            int q = tid + it * 256;
            int r = q >> 5;              // 0..15
            int c = (q & 31) << 2;       // 0..124
            *(float4*)(&Bs[r][c]) = *(const float4*)(W + (size_t)(k0 + r) * DF + c);
        }
        __syncthreads();

        #pragma unroll
        for (int kk = 0; kk < BK; ++kk) {
            float ra[8], rb[8];
            #pragma unroll
            for (int i = 0; i < 8; i++) ra[i] = As[kk][ty * 8 + i];
            #pragma unroll
            for (int j = 0; j < 8; j++) rb[j] = Bs[kk][tx * 8 + j];
            #pragma unroll
            for (int i = 0; i < 8; i++)
                #pragma unroll
                for (int j = 0; j < 8; j++)
                    acc[i][j] = fmaf(ra[i], rb[j], acc[i][j]);
        }
        __syncthreads();
    }

    // --- epilogue: y = acc * dinv[row] (single-array store) ---
    #pragma unroll
    for (int i = 0; i < 8; i++) {
        int grow = rowBase + ty * 8 + i;
        if (grow >= M) continue;
        float di = g_dinv[grow];
        size_t base = (size_t)grow * DF + tx * 8;
        #pragma unroll
        for (int j = 0; j < 8; j += 4) {
            float4 v = make_float4(acc[i][j] * di, acc[i][j + 1] * di,
                                   acc[i][j + 2] * di, acc[i][j + 3] * di);
            *(float4*)(g_y + base + j) = v;
        }
    }
}

// ---------------------------------------------------------------------------
// CSR gather aggregation: warp per node.
//   S[i] = y[i] + sum_{e in in(i)} y[src[e]]        (no atomics, streaming out)
// ---------------------------------------------------------------------------
__global__ void gather_kernel(int N)
{
    int node = (blockIdx.x * blockDim.x + threadIdx.x) >> 5;
    int lane = threadIdx.x & 31;
    if (node >= N) return;
    int beg = g_off[node];
    int end = g_off[node + 1];
    float4 acc = ((const float4*)(g_y + (size_t)node * DF))[lane];   // self term
    for (int e = beg; e < end; e++) {
        int s = g_csr_src[e];
        float4 v = ((const float4*)(g_y + (size_t)s * DF))[lane];
        acc.x += v.x; acc.y += v.y; acc.z += v.z; acc.w += v.w;
    }
    ((float4*)(g_agg + (size_t)node * DF))[lane] = acc;
}

// ---------------------------------------------------------------------------
// Edge decode: z2[i] = S2[i]*dinv[i] + b2;  out[e] = <z2[src], z2[dst]>
// ---------------------------------------------------------------------------
__global__ void edge_dot_kernel(const int* __restrict__ src,
                                const int* __restrict__ dst,
                                const float* __restrict__ bias,
                                float* __restrict__ out,
                                int E)
{
    int warp = (blockIdx.x * blockDim.x + threadIdx.x) >> 5;
    int lane = threadIdx.x & 31;
    if (warp >= E) return;
    int s = __ldg(src + warp);
    int d = __ldg(dst + warp);
    float ds = g_dinv[s];
    float dd = g_dinv[d];
    float4 bb = *(const float4*)(bias + lane * 4);
    float4 a  = *(const float4*)(g_agg + (size_t)s * DF + lane * 4);
    float4 b  = *(const float4*)(g_agg + (size_t)d * DF + lane * 4);
    float p = fmaf(a.x, ds, bb.x) * fmaf(b.x, dd, bb.x)
            + fmaf(a.y, ds, bb.y) * fmaf(b.y, dd, bb.y)
            + fmaf(a.z, ds, bb.z) * fmaf(b.z, dd, bb.z)
            + fmaf(a.w, ds, bb.w) * fmaf(b.w, dd, bb.w);
    #pragma unroll
    for (int o = 16; o > 0; o >>= 1)
        p += __shfl_xor_sync(0xffffffffu, p, o);
    if (lane == 0) out[warp] = p;
}

// ---------------------------------------------------------------------------
// kernel_launch
// Inputs (metadata order): x [N*128], edge_index [2*E], W1, b1, W2, b2
// ---------------------------------------------------------------------------
extern "C" void kernel_launch(void* const* d_in, const int* in_sizes, int n_in,
                              void* d_out, int out_size)
{
    const float* x  = (const float*)d_in[0];
    const int*   ei = (const int*)  d_in[1];
    const float* W1 = (const float*)d_in[2];
    const float* b1 = (const float*)d_in[3];
    const float* W2 = (const float*)d_in[4];
    const float* b2 = (const float*)d_in[5];

    int E = in_sizes[1] / 2;
    int N = in_sizes[0] / DF;
    if (N > MAXN) N = MAXN;
    if (E > MAXE) E = MAXE;

    const int* src = ei;
    const int* dst = ei + E;
    float* out = (float*)d_out;

    const int T = 256;
    int nb = (N + SCAN_B - 1) / SCAN_B;

    // ---- degrees, normalization, CSR build ----
    deg_init_kernel<<<(N + T - 1) / T, T>>>(N);
    deg_count_kernel<<<(E + T - 1) / T, T>>>(dst, E);
    dinv_kernel<<<(N + T - 1) / T, T>>>(N);
    scanA_kernel<<<nb, SCAN_B>>>(N);
    scanB_kernel<<<1, 128>>>(nb);
    scanC_kernel<<<nb, SCAN_B>>>(N);
    csr_fill_kernel<<<(E + T - 1) / T, T>>>(src, dst, E);

    int gemm_blocks = (N + 127) / 128;
    int node_blocks = (N + 7) / 8;   // warp per node, 8 warps/block
    int edge_blocks = (E + 7) / 8;   // warp per edge

    // ---- Layer 1: y1 = (x @ W1) * dinv ; S1 = gather(y1) ----
    gemm_fused_kernel<0, false><<<gemm_blocks, T>>>(x, W1, nullptr, N);
    gather_kernel<<<node_blocks, T>>>(N);
    // g_agg = S1 (raw sums; dinv + b1 + relu applied in GEMM2's A-load)

    // ---- Layer 2: y2 = relu(S1*dinv + b1) @ W2 * dinv ; S2 = gather(y2) ----
    gemm_fused_kernel<1, true><<<gemm_blocks, T>>>(nullptr, W2, b1, N);
    gather_kernel<<<node_blocks, T>>>(N);
    // g_agg = S2 (dinv + b2 applied in decode)

    // ---- Decode: per-edge dot of endpoint embeddings ----
    edge_dot_kernel<<<edge_blocks, T>>>(src, dst, b2, out, E);
}